// round 1
// baseline (speedup 1.0000x reference)
#include <cuda_runtime.h>

// ---------------------------------------------------------------------------
// CorticalGrid: 32x32 grid of predictive-coding columns, 20 relaxation steps.
// One CTA per column; 20 sequential step launches (grid-wide dependency via
// the lateral-context term); fp32 register-blocked GEMMs in shared memory.
// ---------------------------------------------------------------------------

constexpr int GRID_H = 32, GRID_W = 32;
constexpr int NCOL   = GRID_H * GRID_W;   // 1024
constexpr int BATCH  = 64;
constexpr int OBJ    = 64;
constexpr int LOC    = 16;
constexpr int SEN    = 64;
constexpr int STEPS  = 20;
constexpr float ETA  = 0.05f;

constexpr int COL_OBJ = BATCH * OBJ;   // 4096
constexpr int COL_LOC = BATCH * LOC;   // 1024
constexpr int COL_SEN = BATCH * SEN;   // 4096

// Device-global scratch (allocation-free rule: __device__ arrays only)
__device__ float g_xobj0[NCOL * COL_OBJ];      // 16.8 MB
__device__ float g_xobj1[NCOL * COL_OBJ];      // 16.8 MB
__device__ float g_xloc [NCOL * COL_LOC];      //  4.2 MB
__device__ float g_patch[NCOL * COL_SEN];      // 16.8 MB
__device__ float g_WtObj[NCOL * OBJ * SEN];    // 16.8 MB  [n][s*64+o]
__device__ float g_WtLoc[NCOL * LOC * SEN];    //  4.2 MB  [n][s*16+l]
__device__ float g_epart[STEPS * NCOL];

// ---------------------------------------------------------------------------
// Prep: zero state, slice patches into (n, b, s), build transposed weights.
// ---------------------------------------------------------------------------
__global__ void prep_kernel(const float* __restrict__ gin,
                            const float* __restrict__ Wobj,
                            const float* __restrict__ Wloc)
{
    const int stride = gridDim.x * blockDim.x;
    for (int i = blockIdx.x * blockDim.x + threadIdx.x; i < NCOL * COL_SEN; i += stride) {
        g_xobj0[i] = 0.0f;
        const int n = i >> 12, r = i & 4095;
        // patch slicing: i = n*4096 + b*64 + s
        const int b  = r >> 6, s = r & 63;
        const int gh = n >> 5, gw = n & 31;
        const int ph = s >> 3, pw = s & 7;
        g_patch[i] = gin[b * 65536 + (gh * 8 + ph) * 256 + gw * 8 + pw];
        // W_obj transpose: i = n*4096 + o*64 + ss
        const int o = r >> 6, ss = r & 63;
        g_WtObj[(n << 12) + ss * 64 + o] = Wobj[i];
    }
    for (int i = blockIdx.x * blockDim.x + threadIdx.x; i < NCOL * COL_LOC; i += stride) {
        g_xloc[i] = 0.0f;
        const int n = i >> 10, r = i & 1023;
        const int l = r >> 6, ss = r & 63;   // W_loc: [n][l*64+ss]
        g_WtLoc[(n << 10) + ss * 16 + l] = Wloc[i];
    }
}

// ---------------------------------------------------------------------------
// One relaxation step. CTA n owns column n. 256 threads.
// Shared: W, Wt, Wl, Wtl, x, xl, ctx, g, red  = 23808 floats = 95232 B.
// ---------------------------------------------------------------------------
__global__ void __launch_bounds__(256) step_kernel(
    const float* __restrict__ Wobj,
    const float* __restrict__ Wloc,
    float* __restrict__ out_x,
    int step)
{
    extern __shared__ float sh[];
    float* sW   = sh;            // [o*64+s]
    float* sWt  = sh + 4096;     // [s*64+o]
    float* sWl  = sh + 8192;     // [l*64+s]
    float* sWtl = sh + 9216;     // [s*16+l]
    float* sx   = sh + 10240;    // [b*64+o]
    float* sxl  = sh + 14336;    // [b*16+l]
    float* sctx = sh + 15360;    // [b*64+o]
    float* sg   = sh + 19456;    // [b*64+s]
    float* sred = sh + 23552;    // 256

    const int n   = blockIdx.x;
    const int tid = threadIdx.x;

    const float* __restrict__ xin = (step & 1) ? g_xobj1 : g_xobj0;
    float* __restrict__ xoutbuf   = (step & 1) ? g_xobj0 : g_xobj1;
    float* __restrict__ xout      = (step == STEPS - 1) ? out_x : xoutbuf;

    // ---- load column-local tensors into shared ----
    {
        const float4* s1 = (const float4*)(Wobj    + ((long)n << 12));
        const float4* s2 = (const float4*)(g_WtObj + ((long)n << 12));
        const float4* s3 = (const float4*)(xin     + ((long)n << 12));
        float4* d1 = (float4*)sW; float4* d2 = (float4*)sWt; float4* d3 = (float4*)sx;
        #pragma unroll
        for (int k = 0; k < 4; k++) {
            d1[tid + 256 * k] = s1[tid + 256 * k];
            d2[tid + 256 * k] = s2[tid + 256 * k];
            d3[tid + 256 * k] = s3[tid + 256 * k];
        }
        ((float4*)sWl )[tid] = ((const float4*)(Wloc    + ((long)n << 10)))[tid];
        ((float4*)sWtl)[tid] = ((const float4*)(g_WtLoc + ((long)n << 10)))[tid];
        ((float4*)sxl )[tid] = ((const float4*)(g_xloc  + ((long)n << 10)))[tid];
    }

    // ---- lateral context: mean of valid 4-neighbours (reads prev-step xin) ----
    {
        const int gh = n >> 5, gw = n & 31;
        const float inv = 1.0f / (float)((gh > 0) + (gh < GRID_H - 1) + (gw > 0) + (gw < GRID_W - 1));
        const int base = tid * 16;
        #pragma unroll
        for (int k = 0; k < 4; k++) {
            const int off = base + k * 4;
            float ax = 0.f, ay = 0.f, az = 0.f, aw = 0.f;
            if (gh > 0)          { float4 v = *(const float4*)&xin[(((long)(n - GRID_W)) << 12) + off]; ax += v.x; ay += v.y; az += v.z; aw += v.w; }
            if (gh < GRID_H - 1) { float4 v = *(const float4*)&xin[(((long)(n + GRID_W)) << 12) + off]; ax += v.x; ay += v.y; az += v.z; aw += v.w; }
            if (gw > 0)          { float4 v = *(const float4*)&xin[(((long)(n - 1))      << 12) + off]; ax += v.x; ay += v.y; az += v.z; aw += v.w; }
            if (gw < GRID_W - 1) { float4 v = *(const float4*)&xin[(((long)(n + 1))      << 12) + off]; ax += v.x; ay += v.y; az += v.z; aw += v.w; }
            float4 o4; o4.x = ax * inv; o4.y = ay * inv; o4.z = az * inv; o4.w = aw * inv;
            *(float4*)&sctx[off] = o4;
        }
    }
    __syncthreads();

    const int b0 = (tid >> 4) << 2;   // batch tile base
    const int c0 = (tid & 15) << 2;   // s-tile (forward) / o-tile (backward)

    // ---- forward: u = x_obj @ W_obj + x_loc @ W_loc ----
    float acc[4][4];
    #pragma unroll
    for (int i = 0; i < 4; i++) { acc[i][0] = 0.f; acc[i][1] = 0.f; acc[i][2] = 0.f; acc[i][3] = 0.f; }

    #pragma unroll 4
    for (int o = 0; o < OBJ; o += 4) {
        float xv[4][4], wv[4][4];
        #pragma unroll
        for (int i = 0; i < 4; i++) { float4 t = *(const float4*)&sx[(b0 + i) * 64 + o];  xv[i][0]=t.x; xv[i][1]=t.y; xv[i][2]=t.z; xv[i][3]=t.w; }
        #pragma unroll
        for (int j = 0; j < 4; j++) { float4 t = *(const float4*)&sW[(o + j) * 64 + c0]; wv[j][0]=t.x; wv[j][1]=t.y; wv[j][2]=t.z; wv[j][3]=t.w; }
        #pragma unroll
        for (int i = 0; i < 4; i++)
            #pragma unroll
            for (int c = 0; c < 4; c++)
                acc[i][c] += xv[i][0]*wv[0][c] + xv[i][1]*wv[1][c] + xv[i][2]*wv[2][c] + xv[i][3]*wv[3][c];
    }
    #pragma unroll
    for (int l = 0; l < LOC; l += 4) {
        float xv[4][4], wv[4][4];
        #pragma unroll
        for (int i = 0; i < 4; i++) { float4 t = *(const float4*)&sxl[(b0 + i) * 16 + l]; xv[i][0]=t.x; xv[i][1]=t.y; xv[i][2]=t.z; xv[i][3]=t.w; }
        #pragma unroll
        for (int j = 0; j < 4; j++) { float4 t = *(const float4*)&sWl[(l + j) * 64 + c0]; wv[j][0]=t.x; wv[j][1]=t.y; wv[j][2]=t.z; wv[j][3]=t.w; }
        #pragma unroll
        for (int i = 0; i < 4; i++)
            #pragma unroll
            for (int c = 0; c < 4; c++)
                acc[i][c] += xv[i][0]*wv[0][c] + xv[i][1]*wv[1][c] + xv[i][2]*wv[2][c] + xv[i][3]*wv[3][c];
    }

    // ---- pointwise: pred, eps, g, energy ----
    float e_acc = 0.f;
    #pragma unroll
    for (int i = 0; i < 4; i++) {
        float4 p = *(const float4*)&g_patch[((long)n << 12) + (b0 + i) * 64 + c0];
        float pv[4] = {p.x, p.y, p.z, p.w};
        #pragma unroll
        for (int c = 0; c < 4; c++) {
            float pr  = tanhf(acc[i][c]);
            float eps = pv[c] - pr;
            e_acc += eps * eps;
            sg[(b0 + i) * 64 + c0 + c] = eps * (1.0f - pr * pr);
        }
    }
    __syncthreads();

    // ---- backward obj: dx_obj = g @ W_obj^T, update x_obj ----
    float acc2[4][4];
    #pragma unroll
    for (int i = 0; i < 4; i++) { acc2[i][0] = 0.f; acc2[i][1] = 0.f; acc2[i][2] = 0.f; acc2[i][3] = 0.f; }

    #pragma unroll 4
    for (int s = 0; s < SEN; s += 4) {
        float gv[4][4], wv[4][4];
        #pragma unroll
        for (int i = 0; i < 4; i++) { float4 t = *(const float4*)&sg[(b0 + i) * 64 + s];  gv[i][0]=t.x; gv[i][1]=t.y; gv[i][2]=t.z; gv[i][3]=t.w; }
        #pragma unroll
        for (int j = 0; j < 4; j++) { float4 t = *(const float4*)&sWt[(s + j) * 64 + c0]; wv[j][0]=t.x; wv[j][1]=t.y; wv[j][2]=t.z; wv[j][3]=t.w; }
        #pragma unroll
        for (int i = 0; i < 4; i++)
            #pragma unroll
            for (int c = 0; c < 4; c++)
                acc2[i][c] += gv[i][0]*wv[0][c] + gv[i][1]*wv[1][c] + gv[i][2]*wv[2][c] + gv[i][3]*wv[3][c];
    }
    #pragma unroll
    for (int i = 0; i < 4; i++) {
        float4 xo = *(const float4*)&sx  [(b0 + i) * 64 + c0];
        float4 cx = *(const float4*)&sctx[(b0 + i) * 64 + c0];
        float4 ov;
        ov.x = xo.x + ETA * (acc2[i][0] + cx.x - xo.x);
        ov.y = xo.y + ETA * (acc2[i][1] + cx.y - xo.y);
        ov.z = xo.z + ETA * (acc2[i][2] + cx.z - xo.z);
        ov.w = xo.w + ETA * (acc2[i][3] + cx.w - xo.w);
        *(float4*)&xout[((long)n << 12) + (b0 + i) * 64 + c0] = ov;
    }

    // ---- backward loc: dx_loc = g @ W_loc^T, update x_loc (in place) ----
    {
        const int bl = tid >> 2;
        const int l0 = (tid & 3) << 2;
        float a3[4] = {0.f, 0.f, 0.f, 0.f};
        #pragma unroll 4
        for (int s = 0; s < SEN; s += 4) {
            float4 gq = *(const float4*)&sg[bl * 64 + s];
            float gs[4] = {gq.x, gq.y, gq.z, gq.w};
            #pragma unroll
            for (int j = 0; j < 4; j++) {
                float4 w = *(const float4*)&sWtl[(s + j) * 16 + l0];
                a3[0] += gs[j] * w.x; a3[1] += gs[j] * w.y;
                a3[2] += gs[j] * w.z; a3[3] += gs[j] * w.w;
            }
        }
        float4 xl = *(const float4*)&sxl[bl * 16 + l0];
        float4 ov;
        ov.x = xl.x + ETA * a3[0]; ov.y = xl.y + ETA * a3[1];
        ov.z = xl.z + ETA * a3[2]; ov.w = xl.w + ETA * a3[3];
        *(float4*)&g_xloc[((long)n << 10) + bl * 16 + l0] = ov;
    }

    // ---- deterministic per-CTA energy reduction ----
    sred[tid] = e_acc;
    __syncthreads();
    #pragma unroll
    for (int w = 128; w > 0; w >>= 1) {
        if (tid < w) sred[tid] += sred[tid + w];
        __syncthreads();
    }
    if (tid == 0) g_epart[step * NCOL + n] = sred[0];
}

// ---------------------------------------------------------------------------
// Finalize: fixed-order sum of 1024 partials per step -> energy_hist in d_out.
// ---------------------------------------------------------------------------
__global__ void finalize_kernel(float* __restrict__ out)
{
    const int step = blockIdx.x;
    const int tid  = threadIdx.x;
    __shared__ float r[256];
    float s = g_epart[step * NCOL + tid]
            + g_epart[step * NCOL + tid + 256]
            + g_epart[step * NCOL + tid + 512]
            + g_epart[step * NCOL + tid + 768];
    r[tid] = s;
    __syncthreads();
    #pragma unroll
    for (int w = 128; w > 0; w >>= 1) {
        if (tid < w) r[tid] += r[tid + w];
        __syncthreads();
    }
    if (tid == 0) out[(long)NCOL * COL_OBJ + step] = 0.5f * r[0];
}

// ---------------------------------------------------------------------------
extern "C" void kernel_launch(void* const* d_in, const int* in_sizes, int n_in,
                              void* d_out, int out_size)
{
    const float* gin  = (const float*)d_in[0];  // global_input (64, 65536)
    const float* Wobj = (const float*)d_in[1];  // (1024, 64, 64)
    const float* Wloc = (const float*)d_in[2];  // (1024, 16, 64)
    float* out = (float*)d_out;                 // x_obj (1024*64*64) ++ energy (20)

    constexpr int SMEM_BYTES = 23808 * (int)sizeof(float);  // 95232
    cudaFuncSetAttribute(step_kernel, cudaFuncAttributeMaxDynamicSharedMemorySize, SMEM_BYTES);

    prep_kernel<<<1024, 256>>>(gin, Wobj, Wloc);
    for (int step = 0; step < STEPS; step++) {
        step_kernel<<<NCOL, 256, SMEM_BYTES>>>(Wobj, Wloc, out, step);
    }
    finalize_kernel<<<STEPS, 256>>>(out);
}